// round 11
// baseline (speedup 1.0000x reference)
#include <cuda_runtime.h>
#include <cuda_bf16.h>
#include <cuda_fp16.h>
#include <cstdint>

#define EMAX 4000000
#define NMAX 250000
#define DIM  64

// ---------------- device scratch (zero-initialized at load; a trailing
// cleanup kernel restores the zeros needed by the next graph replay) --------
__device__ int   g_cnt[NMAX];          // per-row real-edge count
__device__ int   g_rowptr[NMAX];       // exclusive prefix (row start)
__device__ float g_dinv[NMAX];         // rsqrt(deg) incl. self loop
__device__ unsigned long long g_desc[512];  // lookback descriptors
__device__ int   g_rank[EMAX];         // edge's rank within its row
__device__ int   g_ecol[EMAX];         // CSR payload: col only (4B)
__device__ __half2 g_xa[(size_t)NMAX * 32]; // prescaled feature ping (fp16)
__device__ __half2 g_xb[(size_t)NMAX * 32]; // prescaled feature pong

#define FLAG_AGG    (1ULL << 62)
#define FLAG_PREFIX (2ULL << 62)
#define VAL_MASK    ((1ULL << 62) - 1)

// --- 1) histogram + rank recording (4 edges/thread) ------------------------
__global__ void k_count(const int* __restrict__ row, int E) {
    int t = blockIdx.x * blockDim.x + threadIdx.x;
    int e = t * 4;
    if (e + 3 < E) {
        int4 r4 = __ldg((const int4*)(row + e));
        int p0 = atomicAdd(&g_cnt[r4.x], 1);
        int p1 = atomicAdd(&g_cnt[r4.y], 1);
        int p2 = atomicAdd(&g_cnt[r4.z], 1);
        int p3 = atomicAdd(&g_cnt[r4.w], 1);
        *(int4*)&g_rank[e] = make_int4(p0, p1, p2, p3);
    } else {
        for (int i = e; i < E; i++)
            g_rank[i] = atomicAdd(&g_cnt[row[i]], 1);
    }
}

// --- 2) single-pass exclusive scan (decoupled lookback) + dinv + prescale --
__global__ void __launch_bounds__(1024, 1) k_scan(const float* __restrict__ emb, int n) {
    __shared__ int s[1024];
    __shared__ int s_off;
    int b = blockIdx.x;
    int i = b * 1024 + threadIdx.x;
    int v = (i < n) ? g_cnt[i] : 0;
    s[threadIdx.x] = v;
    __syncthreads();
    #pragma unroll
    for (int off = 1; off < 1024; off <<= 1) {
        int x = (threadIdx.x >= off) ? s[threadIdx.x - off] : 0;
        __syncthreads();
        s[threadIdx.x] += x;
        __syncthreads();
    }
    if (threadIdx.x == 0) {
        unsigned long long total = (unsigned long long)s[1023];
        if (b == 0) {
            __threadfence();
            atomicExch(&g_desc[0], FLAG_PREFIX | total);
            s_off = 0;
        } else {
            __threadfence();
            atomicExch(&g_desc[b], FLAG_AGG | total);
            unsigned long long acc = 0;
            int j = b - 1;
            while (true) {
                unsigned long long d = atomicAdd(&g_desc[j], 0ULL);
                unsigned long long f = d >> 62;
                if (f == 2ULL) { acc += (d & VAL_MASK); break; }
                if (f == 1ULL) { acc += (d & VAL_MASK); j--; }
                else __nanosleep(20);
            }
            __threadfence();
            atomicExch(&g_desc[b], FLAG_PREFIX | (acc + total));
            s_off = (int)acc;
        }
    }
    __syncthreads();
    if (i < n) {
        g_rowptr[i] = s_off + s[threadIdx.x] - v;  // exclusive prefix (row start)
        g_dinv[i]   = rsqrtf((float)(v + 1));      // +1 self loop
    }
    // Fused prescale: x0 = fp16(dinv * emb); 16 threads/node, 4 floats each.
    __syncthreads();
    int node0 = b * 1024;
    for (int sweep = 0; sweep < 16; sweep++) {
        int node = node0 + sweep * 64 + (threadIdx.x >> 4);
        int q = threadIdx.x & 15;
        if (node < n) {
            float sc = g_dinv[node];
            float4 f = __ldg((const float4*)(emb + (size_t)node * DIM + q * 4));
            g_xa[(size_t)node * 32 + q * 2]     = __floats2half2_rn(sc * f.x, sc * f.y);
            g_xa[(size_t)node * 32 + q * 2 + 1] = __floats2half2_rn(sc * f.z, sc * f.w);
        }
    }
}

// --- 3) atomic-free scatter: p = rowptr[row] + rank ------------------------
__global__ void k_scatter(const int* __restrict__ row, const int* __restrict__ col, int E) {
    int t = blockIdx.x * blockDim.x + threadIdx.x;
    int e = t * 4;
    if (e + 3 < E) {
        int4 r4 = __ldg((const int4*)(row + e));
        int4 k4 = __ldg((const int4*)(g_rank + e));
        int4 c4 = __ldg((const int4*)(col + e));
        int p0 = __ldg(&g_rowptr[r4.x]) + k4.x;
        int p1 = __ldg(&g_rowptr[r4.y]) + k4.y;
        int p2 = __ldg(&g_rowptr[r4.z]) + k4.z;
        int p3 = __ldg(&g_rowptr[r4.w]) + k4.w;
        g_ecol[p0] = c4.x;
        g_ecol[p1] = c4.y;
        g_ecol[p2] = c4.z;
        g_ecol[p3] = c4.w;
    } else {
        for (int i = e; i < E; i++)
            g_ecol[__ldg(&g_rowptr[row[i]]) + g_rank[i]] = col[i];
    }
}

// --- streaming (evict-first) float2 store ----------------------------------
__device__ __forceinline__ void stcs_f2(float* p, float2 v) {
    asm volatile("st.global.cs.v2.f32 [%0], {%1, %2};" :: "l"(p), "f"(v.x), "f"(v.y) : "memory");
}

// --- 4) atomic-free warp-per-row SpMM on fp16 prescaled features -----------
// out[r] = dinv[r] * (sum_e x[col_e] + x[r]);  xnext[r] = fp16(dinv[r]*out[r]).
// Col indices double-buffered to overlap the index load with the gathers.
__global__ void __launch_bounds__(256) k_spmm(
        const __half2* __restrict__ gx,
        float* __restrict__ out,           // stride 192 (permuted slot)
        __half2* __restrict__ xnext,       // 32 half2 per row, or nullptr
        float* __restrict__ dup,           // stride 64 fp32, or nullptr
        int n) {
    int r    = (blockIdx.x * blockDim.x + threadIdx.x) >> 5;
    int lane = threadIdx.x & 31;
    if (r >= n) return;

    const __half2* base = gx + lane;
    float2 a = __half22float2(__ldg(base + (size_t)r * 32));  // x[r] (self)
    float ax = a.x, ay = a.y;

    int p  = __ldg(&g_rowptr[r]);              // row start
    int pe = p + __ldg(&g_cnt[r]);             // row end

    while (p < pe && (p & 3)) {                // align for LDG.128 on cols
        int c = __ldg(&g_ecol[p]);
        float2 f = __half22float2(__ldg(base + (size_t)c * 32));
        ax += f.x; ay += f.y;
        p++;
    }

    int nloops = (pe - p) >> 3;
    if (nloops > 0) {
        int4 a0 = __ldg((const int4*)&g_ecol[p]);
        int4 a1 = __ldg((const int4*)&g_ecol[p + 4]);
        for (int it = 0; it < nloops; it++) {
            int4 c0 = a0, c1 = a1;
            int np = p + 8;
            if (it + 1 < nloops) {             // prefetch next 8 cols
                a0 = __ldg((const int4*)&g_ecol[np]);
                a1 = __ldg((const int4*)&g_ecol[np + 4]);
            }
            float2 f0 = __half22float2(__ldg(base + (size_t)c0.x * 32));
            float2 f1 = __half22float2(__ldg(base + (size_t)c0.y * 32));
            float2 f2 = __half22float2(__ldg(base + (size_t)c0.z * 32));
            float2 f3 = __half22float2(__ldg(base + (size_t)c0.w * 32));
            float2 f4 = __half22float2(__ldg(base + (size_t)c1.x * 32));
            float2 f5 = __half22float2(__ldg(base + (size_t)c1.y * 32));
            float2 f6 = __half22float2(__ldg(base + (size_t)c1.z * 32));
            float2 f7 = __half22float2(__ldg(base + (size_t)c1.w * 32));
            ax += f0.x + f1.x + f2.x + f3.x + f4.x + f5.x + f6.x + f7.x;
            ay += f0.y + f1.y + f2.y + f3.y + f4.y + f5.y + f6.y + f7.y;
            p = np;
        }
    }
    if (p + 3 < pe) {
        int4 c0 = __ldg((const int4*)&g_ecol[p]);
        float2 f0 = __half22float2(__ldg(base + (size_t)c0.x * 32));
        float2 f1 = __half22float2(__ldg(base + (size_t)c0.y * 32));
        float2 f2 = __half22float2(__ldg(base + (size_t)c0.z * 32));
        float2 f3 = __half22float2(__ldg(base + (size_t)c0.w * 32));
        ax += f0.x + f1.x + f2.x + f3.x;
        ay += f0.y + f1.y + f2.y + f3.y;
        p += 4;
    }
    for (; p < pe; p++) {
        int c = __ldg(&g_ecol[p]);
        float2 f = __half22float2(__ldg(base + (size_t)c * 32));
        ax += f.x; ay += f.y;
    }

    float s = g_dinv[r];
    float ox = s * ax, oy = s * ay;
    stcs_f2(out + (size_t)r * 192 + lane * 2, make_float2(ox, oy));
    if (xnext)
        xnext[(size_t)r * 32 + lane] = __floats2half2_rn(s * ox, s * oy);
    if (dup)
        stcs_f2(dup + (size_t)r * DIM + lane * 2, make_float2(ox, oy));
}

// --- 5) cleanup: restore zeros for the next graph replay -------------------
__global__ void k_cleanup(int n) {
    int i = blockIdx.x * blockDim.x + threadIdx.x;
    if (i < n) g_cnt[i] = 0;
    if (i < 512) g_desc[i] = 0ULL;
}

// ---------------------------------------------------------------------------
extern "C" void kernel_launch(void* const* d_in, const int* in_sizes, int n_in,
                              void* d_out, int out_size) {
    const int* edge_index = (const int*)d_in[0];
    const float* emb      = (const float*)d_in[1];

    const int E = in_sizes[0] / 2;     // edge_index is (2, E) row-major
    const int n = in_sizes[1] / DIM;   // number of nodes

    const int* row = edge_index;
    const int* col = edge_index + E;

    float* out = (float*)d_out;
    // LAYER_PERM = (2,0,1): [0:64)=feats[2], [64:128)=feats[0], [128:192)=feats[1];
    // then feat (== feats[2]) again contiguously at n*192 if out_size covers it.
    float* f1 = out + 64;    // stride 192
    float* f2 = out + 128;   // stride 192
    float* f3 = out + 0;     // stride 192
    bool want_dup = ((long long)out_size >= (long long)n * 256);
    float* dup = want_dup ? (out + (size_t)n * 192) : nullptr;

    const int B = 256;
    const int q4 = (E + 3) / 4;

    __half2* xa; cudaGetSymbolAddress((void**)&xa, g_xa);
    __half2* xb; cudaGetSymbolAddress((void**)&xb, g_xb);

    // Launch sequence (g_cnt / g_desc are zero at entry: BSS on first call,
    // k_cleanup on subsequent replays).
    k_count<<<(q4 + B - 1) / B, B>>>(row, E);              // 0
    k_scan<<<(n + 1023) / 1024, 1024>>>(emb, n);           // 1
    k_scatter<<<(q4 + B - 1) / B, B>>>(row, col, E);       // 2

    const int spmm_blocks = (n * 32 + B - 1) / B;
    k_spmm<<<spmm_blocks, B>>>(xa, f1, xb, nullptr, n);    // 3: layer 1
    k_spmm<<<spmm_blocks, B>>>(xb, f2, xa, nullptr, n);    // 4: layer 2
    k_spmm<<<spmm_blocks, B>>>(xa, f3, nullptr, dup, n);   // 5: layer 3

    k_cleanup<<<(n + B - 1) / B, B>>>(n);                  // 6
}

// round 13
// speedup vs baseline: 1.4387x; 1.4387x over previous
#include <cuda_runtime.h>
#include <cuda_bf16.h>
#include <cuda_fp16.h>
#include <cstdint>

#define EMAX 4000000
#define NMAX 250000
#define DIM  64

// ---------------- device scratch (zero-initialized at load; trailing
// cleanup kernel restores zeros for the next graph replay) ------------------
__device__ int   g_cnt[NMAX];          // per-row real-edge count
__device__ int   g_rowptr[NMAX];       // excl. prefix; scatter advances to row end
__device__ float g_dinv[NMAX];         // rsqrt(deg) incl. self loop
__device__ unsigned long long g_desc[512];  // lookback descriptors
__device__ int   g_ecol[EMAX];         // CSR payload: col only (4B)
__device__ uint4 g_xa[(size_t)NMAX * 8];  // prescaled fp16 features ping (128B/row)
__device__ uint4 g_xb[(size_t)NMAX * 8];  // prescaled fp16 features pong

#define FLAG_AGG    (1ULL << 62)
#define FLAG_PREFIX (2ULL << 62)
#define VAL_MASK    ((1ULL << 62) - 1)

// --- 1) degree histogram (4 edges/thread, no atomic return -> RED) ---------
__global__ void k_count(const int* __restrict__ row, int E) {
    int t = blockIdx.x * blockDim.x + threadIdx.x;
    int e = t * 4;
    if (e + 3 < E) {
        int4 r4 = __ldg((const int4*)(row + e));
        atomicAdd(&g_cnt[r4.x], 1);
        atomicAdd(&g_cnt[r4.y], 1);
        atomicAdd(&g_cnt[r4.z], 1);
        atomicAdd(&g_cnt[r4.w], 1);
    } else {
        for (int i = e; i < E; i++) atomicAdd(&g_cnt[row[i]], 1);
    }
}

// --- 2) single-pass exclusive scan (decoupled lookback) + dinv + prescale --
__global__ void __launch_bounds__(1024, 1) k_scan(const float* __restrict__ emb, int n) {
    __shared__ int s[1024];
    __shared__ int s_off;
    int b = blockIdx.x;
    int i = b * 1024 + threadIdx.x;
    int v = (i < n) ? g_cnt[i] : 0;
    s[threadIdx.x] = v;
    __syncthreads();
    #pragma unroll
    for (int off = 1; off < 1024; off <<= 1) {
        int x = (threadIdx.x >= off) ? s[threadIdx.x - off] : 0;
        __syncthreads();
        s[threadIdx.x] += x;
        __syncthreads();
    }
    if (threadIdx.x == 0) {
        unsigned long long total = (unsigned long long)s[1023];
        if (b == 0) {
            __threadfence();
            atomicExch(&g_desc[0], FLAG_PREFIX | total);
            s_off = 0;
        } else {
            __threadfence();
            atomicExch(&g_desc[b], FLAG_AGG | total);
            unsigned long long acc = 0;
            int j = b - 1;
            while (true) {
                unsigned long long d = atomicAdd(&g_desc[j], 0ULL);
                unsigned long long f = d >> 62;
                if (f == 2ULL) { acc += (d & VAL_MASK); break; }
                if (f == 1ULL) { acc += (d & VAL_MASK); j--; }
                else __nanosleep(20);
            }
            __threadfence();
            atomicExch(&g_desc[b], FLAG_PREFIX | (acc + total));
            s_off = (int)acc;
        }
    }
    __syncthreads();
    if (i < n) {
        g_rowptr[i] = s_off + s[threadIdx.x] - v;  // exclusive prefix (row start)
        g_dinv[i]   = rsqrtf((float)(v + 1));      // +1 self loop
    }
    // Fused prescale: x0 = fp16(dinv * emb); 16 threads/node, 4 floats each.
    __syncthreads();
    int node0 = b * 1024;
    uint2* xa2 = (uint2*)g_xa;
    for (int sweep = 0; sweep < 16; sweep++) {
        int node = node0 + sweep * 64 + (threadIdx.x >> 4);
        int q = threadIdx.x & 15;
        if (node < n) {
            float sc = g_dinv[node];
            float4 f = __ldg((const float4*)(emb + (size_t)node * DIM + q * 4));
            __half2 h0 = __floats2half2_rn(sc * f.x, sc * f.y);
            __half2 h1 = __floats2half2_rn(sc * f.z, sc * f.w);
            xa2[(size_t)node * 16 + q] = make_uint2(*(unsigned*)&h0, *(unsigned*)&h1);
        }
    }
}

// --- 3) counting-sort scatter: advances g_rowptr to row end ----------------
__global__ void k_scatter(const int* __restrict__ row, const int* __restrict__ col, int E) {
    int t = blockIdx.x * blockDim.x + threadIdx.x;
    int e = t * 4;
    if (e + 3 < E) {
        int4 r4 = __ldg((const int4*)(row + e));
        int4 c4 = __ldg((const int4*)(col + e));
        int p0 = atomicAdd(&g_rowptr[r4.x], 1);
        int p1 = atomicAdd(&g_rowptr[r4.y], 1);
        int p2 = atomicAdd(&g_rowptr[r4.z], 1);
        int p3 = atomicAdd(&g_rowptr[r4.w], 1);
        g_ecol[p0] = c4.x;
        g_ecol[p1] = c4.y;
        g_ecol[p2] = c4.z;
        g_ecol[p3] = c4.w;
    } else {
        for (int i = e; i < E; i++) {
            int p = atomicAdd(&g_rowptr[row[i]], 1);
            g_ecol[p] = col[i];
        }
    }
}

// --- streaming (evict-first) float4 store ----------------------------------
__device__ __forceinline__ void stcs_f4(float* p, float4 v) {
    asm volatile("st.global.cs.v4.f32 [%0], {%1, %2, %3, %4};"
                 :: "l"(p), "f"(v.x), "f"(v.y), "f"(v.z), "f"(v.w) : "memory");
}

__device__ __forceinline__ void acc_u4(float4& a0, float4& a1, uint4 g) {
    float2 t;
    t = __half22float2(*(__half2*)&g.x); a0.x += t.x; a0.y += t.y;
    t = __half22float2(*(__half2*)&g.y); a0.z += t.x; a0.w += t.y;
    t = __half22float2(*(__half2*)&g.z); a1.x += t.x; a1.y += t.y;
    t = __half22float2(*(__half2*)&g.w); a1.z += t.x; a1.w += t.y;
}

// --- 4) SpMM: 4 rows per warp, 8 lanes per row, 16B (8 fp16 cols) per lane -
// One gather LDG instruction serves 4 edges (one per row slot); one col-index
// LDG serves 4 rows. Each lane owns its 8 columns -> no cross-lane reduce.
// out[r] = dinv[r] * (sum_e x[col_e] + x[r]);  xnext[r] = fp16(dinv[r]*out[r]).
__global__ void __launch_bounds__(256) k_spmm(
        const uint4* __restrict__ gx,
        float* __restrict__ out,           // stride 192 (permuted slot)
        uint4* __restrict__ xnext,         // 8 uint4 per row, or nullptr
        float* __restrict__ dup,           // stride 64 fp32, or nullptr
        int n) {
    int warpId = (blockIdx.x * blockDim.x + threadIdx.x) >> 5;
    int lane = threadIdx.x & 31;
    int slot = lane >> 3;                  // 0..3: which row of this warp
    int sub  = lane & 7;                   // 0..7: cols [sub*8, sub*8+8)
    int r = warpId * 4 + slot;
    bool rowok = (r < n);
    int rr = rowok ? r : 0;

    float4 a0, a1;
    {
        uint4 u = __ldg(&gx[(size_t)rr * 8 + sub]);   // x[r] self term
        float2 t;
        t = __half22float2(*(__half2*)&u.x); a0 = make_float4(t.x, t.y, 0.f, 0.f);
        t = __half22float2(*(__half2*)&u.y); a0.z = t.x; a0.w = t.y;
        t = __half22float2(*(__half2*)&u.z); a1 = make_float4(t.x, t.y, 0.f, 0.f);
        t = __half22float2(*(__half2*)&u.w); a1.z = t.x; a1.w = t.y;
    }

    int pe  = rowok ? __ldg(&g_rowptr[rr]) : 0;   // post-scatter = row end
    int len = rowok ? __ldg(&g_cnt[rr]) : 0;
    int p   = pe - len;

    for (; p < pe; p += 4) {
        int e1 = p + 1, e2 = p + 2, e3 = p + 3;
        int c0 = __ldg(&g_ecol[p]);
        int c1 = (e1 < pe) ? __ldg(&g_ecol[e1]) : rr;
        int c2 = (e2 < pe) ? __ldg(&g_ecol[e2]) : rr;
        int c3 = (e3 < pe) ? __ldg(&g_ecol[e3]) : rr;
        uint4 g0 = __ldg(&gx[(size_t)c0 * 8 + sub]);
        uint4 g1 = __ldg(&gx[(size_t)c1 * 8 + sub]);
        uint4 g2 = __ldg(&gx[(size_t)c2 * 8 + sub]);
        uint4 g3 = __ldg(&gx[(size_t)c3 * 8 + sub]);
        acc_u4(a0, a1, g0);
        if (e1 < pe) acc_u4(a0, a1, g1);
        if (e2 < pe) acc_u4(a0, a1, g2);
        if (e3 < pe) acc_u4(a0, a1, g3);
    }

    if (rowok) {
        float s = __ldg(&g_dinv[r]);
        float4 o0 = make_float4(s * a0.x, s * a0.y, s * a0.z, s * a0.w);
        float4 o1 = make_float4(s * a1.x, s * a1.y, s * a1.z, s * a1.w);
        float* orow = out + (size_t)r * 192 + sub * 8;
        stcs_f4(orow, o0);
        stcs_f4(orow + 4, o1);
        if (xnext) {
            __half2 q0 = __floats2half2_rn(s * o0.x, s * o0.y);
            __half2 q1 = __floats2half2_rn(s * o0.z, s * o0.w);
            __half2 q2 = __floats2half2_rn(s * o1.x, s * o1.y);
            __half2 q3 = __floats2half2_rn(s * o1.z, s * o1.w);
            xnext[(size_t)r * 8 + sub] =
                make_uint4(*(unsigned*)&q0, *(unsigned*)&q1,
                           *(unsigned*)&q2, *(unsigned*)&q3);
        }
        if (dup) {
            float* drow = dup + (size_t)r * DIM + sub * 8;
            stcs_f4(drow, o0);
            stcs_f4(drow + 4, o1);
        }
    }
}

// --- 5) cleanup: restore zeros for the next graph replay -------------------
__global__ void k_cleanup(int n) {
    int i = blockIdx.x * blockDim.x + threadIdx.x;
    if (i < n) g_cnt[i] = 0;
    if (i < 512) g_desc[i] = 0ULL;
}

// ---------------------------------------------------------------------------
extern "C" void kernel_launch(void* const* d_in, const int* in_sizes, int n_in,
                              void* d_out, int out_size) {
    const int* edge_index = (const int*)d_in[0];
    const float* emb      = (const float*)d_in[1];

    const int E = in_sizes[0] / 2;     // edge_index is (2, E) row-major
    const int n = in_sizes[1] / DIM;   // number of nodes

    const int* row = edge_index;
    const int* col = edge_index + E;

    float* out = (float*)d_out;
    // LAYER_PERM = (2,0,1): [0:64)=feats[2], [64:128)=feats[0], [128:192)=feats[1];
    // then feat (== feats[2]) again contiguously at n*192 if out_size covers it.
    float* f1 = out + 64;    // stride 192
    float* f2 = out + 128;   // stride 192
    float* f3 = out + 0;     // stride 192
    bool want_dup = ((long long)out_size >= (long long)n * 256);
    float* dup = want_dup ? (out + (size_t)n * 192) : nullptr;

    const int B = 256;
    const int q4 = (E + 3) / 4;

    uint4* xa; cudaGetSymbolAddress((void**)&xa, g_xa);
    uint4* xb; cudaGetSymbolAddress((void**)&xb, g_xb);

    // g_cnt / g_desc are zero at entry (BSS on first call, k_cleanup after).
    k_count<<<(q4 + B - 1) / B, B>>>(row, E);              // 0
    k_scan<<<(n + 1023) / 1024, 1024>>>(emb, n);           // 1
    k_scatter<<<(q4 + B - 1) / B, B>>>(row, col, E);       // 2

    // SpMM: 4 rows/warp -> 32 rows per 256-thread block
    const int spmm_blocks = (n + 31) / 32;
    k_spmm<<<spmm_blocks, B>>>(xa, f1, xb, nullptr, n);    // 3: layer 1
    k_spmm<<<spmm_blocks, B>>>(xb, f2, xa, nullptr, n);    // 4: layer 2
    k_spmm<<<spmm_blocks, B>>>(xa, f3, nullptr, dup, n);   // 5: layer 3

    k_cleanup<<<(n + B - 1) / B, B>>>(n);                  // 6
}

// round 14
// speedup vs baseline: 1.6929x; 1.1766x over previous
#include <cuda_runtime.h>
#include <cuda_bf16.h>
#include <cuda_fp16.h>
#include <cstdint>

#define EMAX  4000000
#define NMAX  250000
#define DIM   64
// padded CSR capacity: E + 3 per row, rounded up
#define EPADMAX (EMAX + 3 * NMAX + 64)

// ---------------- device scratch (zero-initialized at load; trailing
// cleanup kernel restores zeros for the next graph replay) ------------------
__device__ int   g_cnt[NMAX];          // per-row real-edge count
__device__ int   g_rowptr[NMAX];       // padded excl. prefix; scatter advances
__device__ float g_dinv[NMAX];         // rsqrt(deg) incl. self loop
__device__ unsigned long long g_desc[512];  // lookback descriptors
__device__ int   g_ecol[EPADMAX];      // padded CSR cols (dummy = n)
__device__ uint4 g_xa[(size_t)(NMAX + 1) * 8]; // fp16 features ping; row n = 0
__device__ uint4 g_xb[(size_t)(NMAX + 1) * 8]; // fp16 features pong; row n = 0

#define FLAG_AGG    (1ULL << 62)
#define FLAG_PREFIX (2ULL << 62)
#define VAL_MASK    ((1ULL << 62) - 1)

// --- 1) degree histogram (4 edges/thread) + prefill padded CSR with dummy --
__global__ void k_count(const int* __restrict__ row, int E, int epad4, int dummy) {
    int t = blockIdx.x * blockDim.x + threadIdx.x;
    // prefill: contiguous int4 stores of the dummy index
    if (t < epad4)
        *(int4*)&g_ecol[t * 4] = make_int4(dummy, dummy, dummy, dummy);
    int e = t * 4;
    if (e + 3 < E) {
        int4 r4 = __ldg((const int4*)(row + e));
        atomicAdd(&g_cnt[r4.x], 1);
        atomicAdd(&g_cnt[r4.y], 1);
        atomicAdd(&g_cnt[r4.z], 1);
        atomicAdd(&g_cnt[r4.w], 1);
    } else {
        for (int i = e; i < E; i++) atomicAdd(&g_cnt[row[i]], 1);
    }
}

// --- 2) single-pass exclusive scan of PADDED counts + dinv + prescale ------
__global__ void __launch_bounds__(1024, 1) k_scan(const float* __restrict__ emb, int n) {
    __shared__ int s[1024];
    __shared__ int s_off;
    int b = blockIdx.x;
    int i = b * 1024 + threadIdx.x;
    int v  = (i < n) ? g_cnt[i] : 0;
    int pv = (v + 3) & ~3;                 // padded row length
    s[threadIdx.x] = pv;
    __syncthreads();
    #pragma unroll
    for (int off = 1; off < 1024; off <<= 1) {
        int x = (threadIdx.x >= off) ? s[threadIdx.x - off] : 0;
        __syncthreads();
        s[threadIdx.x] += x;
        __syncthreads();
    }
    if (threadIdx.x == 0) {
        unsigned long long total = (unsigned long long)s[1023];
        if (b == 0) {
            __threadfence();
            atomicExch(&g_desc[0], FLAG_PREFIX | total);
            s_off = 0;
        } else {
            __threadfence();
            atomicExch(&g_desc[b], FLAG_AGG | total);
            unsigned long long acc = 0;
            int j = b - 1;
            while (true) {
                unsigned long long d = atomicAdd(&g_desc[j], 0ULL);
                unsigned long long f = d >> 62;
                if (f == 2ULL) { acc += (d & VAL_MASK); break; }
                if (f == 1ULL) { acc += (d & VAL_MASK); j--; }
                else __nanosleep(20);
            }
            __threadfence();
            atomicExch(&g_desc[b], FLAG_PREFIX | (acc + total));
            s_off = (int)acc;
        }
    }
    __syncthreads();
    if (i < n) {
        g_rowptr[i] = s_off + s[threadIdx.x] - pv; // padded row start (4-aligned)
        g_dinv[i]   = rsqrtf((float)(v + 1));      // +1 self loop
    }
    // Fused prescale: x0 = fp16(dinv * emb); 16 threads/node, 4 floats each.
    __syncthreads();
    int node0 = b * 1024;
    uint2* xa2 = (uint2*)g_xa;
    for (int sweep = 0; sweep < 16; sweep++) {
        int node = node0 + sweep * 64 + (threadIdx.x >> 4);
        int q = threadIdx.x & 15;
        if (node < n) {
            float sc = g_dinv[node];
            float4 f = __ldg((const float4*)(emb + (size_t)node * DIM + q * 4));
            __half2 h0 = __floats2half2_rn(sc * f.x, sc * f.y);
            __half2 h1 = __floats2half2_rn(sc * f.z, sc * f.w);
            xa2[(size_t)node * 16 + q] = make_uint2(*(unsigned*)&h0, *(unsigned*)&h1);
        }
    }
}

// --- 3) counting-sort scatter: advances g_rowptr toward row end ------------
__global__ void k_scatter(const int* __restrict__ row, const int* __restrict__ col, int E) {
    int t = blockIdx.x * blockDim.x + threadIdx.x;
    int e = t * 4;
    if (e + 3 < E) {
        int4 r4 = __ldg((const int4*)(row + e));
        int4 c4 = __ldg((const int4*)(col + e));
        int p0 = atomicAdd(&g_rowptr[r4.x], 1);
        int p1 = atomicAdd(&g_rowptr[r4.y], 1);
        int p2 = atomicAdd(&g_rowptr[r4.z], 1);
        int p3 = atomicAdd(&g_rowptr[r4.w], 1);
        g_ecol[p0] = c4.x;
        g_ecol[p1] = c4.y;
        g_ecol[p2] = c4.z;
        g_ecol[p3] = c4.w;
    } else {
        for (int i = e; i < E; i++) {
            int p = atomicAdd(&g_rowptr[row[i]], 1);
            g_ecol[p] = col[i];
        }
    }
}

// --- streaming (evict-first) float4 store ----------------------------------
__device__ __forceinline__ void stcs_f4(float* p, float4 v) {
    asm volatile("st.global.cs.v4.f32 [%0], {%1, %2, %3, %4};"
                 :: "l"(p), "f"(v.x), "f"(v.y), "f"(v.z), "f"(v.w) : "memory");
}

__device__ __forceinline__ void acc_u4(float4& a0, float4& a1, uint4 g) {
    float2 t;
    t = __half22float2(*(__half2*)&g.x); a0.x += t.x; a0.y += t.y;
    t = __half22float2(*(__half2*)&g.y); a0.z += t.x; a0.w += t.y;
    t = __half22float2(*(__half2*)&g.z); a1.x += t.x; a1.y += t.y;
    t = __half22float2(*(__half2*)&g.w); a1.z += t.x; a1.w += t.y;
}

// --- 4) SpMM on padded CSR: 4 rows/warp, 8 lanes/row, 16B per lane ---------
// Branch-free inner loop: int4 index load (one LDG per 4 edges) + 4
// unconditional gathers (padding points at the all-zero dummy row).
__global__ void __launch_bounds__(256) k_spmm(
        const uint4* __restrict__ gx,
        float* __restrict__ out,           // stride 192 (permuted slot)
        uint4* __restrict__ xnext,         // 8 uint4 per row, or nullptr
        float* __restrict__ dup,           // stride 64 fp32, or nullptr
        int n) {
    int warpId = (blockIdx.x * blockDim.x + threadIdx.x) >> 5;
    int lane = threadIdx.x & 31;
    int slot = lane >> 3;                  // 0..3: row slot within warp
    int sub  = lane & 7;                   // 0..7: cols [sub*8, sub*8+8)
    int r = warpId * 4 + slot;
    bool rowok = (r < n);
    int rr = rowok ? r : 0;

    float4 a0, a1;
    {
        uint4 u = __ldg(&gx[(size_t)rr * 8 + sub]);   // x[r] self term
        float2 t;
        t = __half22float2(*(__half2*)&u.x); a0 = make_float4(t.x, t.y, 0.f, 0.f);
        t = __half22float2(*(__half2*)&u.y); a0.z = t.x; a0.w = t.y;
        t = __half22float2(*(__half2*)&u.z); a1 = make_float4(t.x, t.y, 0.f, 0.f);
        t = __half22float2(*(__half2*)&u.w); a1.z = t.x; a1.w = t.y;
    }

    int len  = rowok ? __ldg(&g_cnt[rr]) : 0;
    int pecur = rowok ? __ldg(&g_rowptr[rr]) : 0;  // = start + len (post-scatter)
    int p    = pecur - len;                         // padded start (4-aligned)
    int pend = p + ((len + 3) & ~3);                // padded end

    for (; p < pend; p += 4) {
        int4 c = __ldg((const int4*)&g_ecol[p]);
        uint4 g0 = __ldg(&gx[(size_t)c.x * 8 + sub]);
        uint4 g1 = __ldg(&gx[(size_t)c.y * 8 + sub]);
        uint4 g2 = __ldg(&gx[(size_t)c.z * 8 + sub]);
        uint4 g3 = __ldg(&gx[(size_t)c.w * 8 + sub]);
        acc_u4(a0, a1, g0);
        acc_u4(a0, a1, g1);
        acc_u4(a0, a1, g2);
        acc_u4(a0, a1, g3);
    }

    if (rowok) {
        float s = __ldg(&g_dinv[r]);
        float4 o0 = make_float4(s * a0.x, s * a0.y, s * a0.z, s * a0.w);
        float4 o1 = make_float4(s * a1.x, s * a1.y, s * a1.z, s * a1.w);
        float* orow = out + (size_t)r * 192 + sub * 8;
        stcs_f4(orow, o0);
        stcs_f4(orow + 4, o1);
        if (xnext) {
            __half2 q0 = __floats2half2_rn(s * o0.x, s * o0.y);
            __half2 q1 = __floats2half2_rn(s * o0.z, s * o0.w);
            __half2 q2 = __floats2half2_rn(s * o1.x, s * o1.y);
            __half2 q3 = __floats2half2_rn(s * o1.z, s * o1.w);
            xnext[(size_t)r * 8 + sub] =
                make_uint4(*(unsigned*)&q0, *(unsigned*)&q1,
                           *(unsigned*)&q2, *(unsigned*)&q3);
        }
        if (dup) {
            float* drow = dup + (size_t)r * DIM + sub * 8;
            stcs_f4(drow, o0);
            stcs_f4(drow + 4, o1);
        }
    }
}

// --- 5) cleanup: restore zeros for the next graph replay -------------------
__global__ void k_cleanup(int n) {
    int i = blockIdx.x * blockDim.x + threadIdx.x;
    if (i < n) g_cnt[i] = 0;
    if (i < 512) g_desc[i] = 0ULL;
}

// ---------------------------------------------------------------------------
extern "C" void kernel_launch(void* const* d_in, const int* in_sizes, int n_in,
                              void* d_out, int out_size) {
    const int* edge_index = (const int*)d_in[0];
    const float* emb      = (const float*)d_in[1];

    const int E = in_sizes[0] / 2;     // edge_index is (2, E) row-major
    const int n = in_sizes[1] / DIM;   // number of nodes

    const int* row = edge_index;
    const int* col = edge_index + E;

    float* out = (float*)d_out;
    // LAYER_PERM = (2,0,1): [0:64)=feats[2], [64:128)=feats[0], [128:192)=feats[1];
    // then feat (== feats[2]) again contiguously at n*192 if out_size covers it.
    float* f1 = out + 64;    // stride 192
    float* f2 = out + 128;   // stride 192
    float* f3 = out + 0;     // stride 192
    bool want_dup = ((long long)out_size >= (long long)n * 256);
    float* dup = want_dup ? (out + (size_t)n * 192) : nullptr;

    const int B = 256;
    const int q4 = (E + 3) / 4;
    const int epad = E + 3 * n + 16;       // upper bound on padded CSR size
    const int epad4 = (epad + 3) / 4;
    const int cnt_grid = (epad4 > q4 ? epad4 : q4);

    uint4* xa; cudaGetSymbolAddress((void**)&xa, g_xa);
    uint4* xb; cudaGetSymbolAddress((void**)&xb, g_xb);

    // g_cnt / g_desc are zero at entry (BSS on first call, k_cleanup after).
    k_count<<<(cnt_grid + B - 1) / B, B>>>(row, E, epad4, n);  // 0
    k_scan<<<(n + 1023) / 1024, 1024>>>(emb, n);               // 1
    k_scatter<<<(q4 + B - 1) / B, B>>>(row, col, E);           // 2

    // SpMM: 4 rows/warp -> 32 rows per 256-thread block
    const int spmm_blocks = (n + 31) / 32;
    k_spmm<<<spmm_blocks, B>>>(xa, f1, xb, nullptr, n);        // 3: layer 1
    k_spmm<<<spmm_blocks, B>>>(xb, f2, xa, nullptr, n);        // 4: layer 2
    k_spmm<<<spmm_blocks, B>>>(xa, f3, nullptr, dup, n);       // 5: layer 3

    k_cleanup<<<(n + B - 1) / B, B>>>(n);                      // 6
}